// round 15
// baseline (speedup 1.0000x reference)
#include <cuda_runtime.h>
#include <cuda_fp16.h>
#include <math.h>
#include <stdint.h>

// Problem constants: B=2, S=1024 -> T=2048 tokens; D=768; E=8 experts; DFF=3072; top-2.
#define T    2048
#define D    768
#define E    8
#define DFF  3072

// GEMM tiling: 128x256 CTA tile, 256 threads (8 warps, 2x4), 64x64 warp tiles,
// BK=64 (4 sub-k16 per sync), fp16 mma.sync + ldmatrix, 3-stage cp.async.
// ONE persistent mega-kernel runs cvt + router + GEMM1 + GEMM2 + combine via a
// global work queue with dependency counters (aux concurrency + no launch gaps).
#define BM 128
#define BN 256
#define BK 64
#define SA 72                       // smem row stride (halves): 64 + 8 pad
#define STAGES 3
#define STG_ROWS (BM + BN)          // 384 rows (A then B) per stage
#define STG_BYTES (STG_ROWS * SA * 2)   // 55296 B per stage
#define SMEM_TOT (STAGES * STG_BYTES)   // 165888 B
#define SPLITK 4
#define NSM 148
#define NKT 12                      // both GEMMs: K=768 per pass / BK=64

// ---- work queue layout ----
#define NA   32                     // cvt-x items (196608 chunks / 6144)
#define NB   256                    // router items (8 tokens each)
#define NC   192                    // cvt-W1 items (2359296 chunks / 12288)
#define ND   192                    // cvt-W2 items
#define NG1  1536                   // GEMM1 tiles (12 x 16 x 8)
#define NG2  1536                   // GEMM2 tiles (3 x 16 x 32)
#define NCB  64                     // combine items (32 tokens each)
#define OB   (NA)
#define OC   (OB + NB)
#define OD   (OC + NC)
#define OG1  (OD + ND)
#define OG2  (OG1 + NG1)
#define OCB  (OG2 + NG2)
#define NTOT_Q (OCB + NCB)
#define AUX1_TGT (NA + NB + NC)     // gates GEMM1 (x-cvt + router + W1-cvt)
#define AUX2_TGT (ND)               // gates GEMM2 (W2-cvt)
#define DEP_TARGET 48               // GEMM1 tiles per (e, sK)

// ---------------------------------------------------------------------------
// Device scratch
// ---------------------------------------------------------------------------
__device__ int    g_cnt[E];
__device__ int    g_tok[E * T];
__device__ int    g_rowof[T * 2];
__device__ float  g_w[T * 2];
__device__ int    g_q;
__device__ int    g_aux1, g_aux2, g_g2;
__device__ int    g_done[E * SPLITK];
__device__ __half g_xh[T * D];
__device__ __half g_W1h[(size_t)E * DFF * D];
__device__ __half g_W2h[(size_t)E * D * DFF];
__device__ __half g_Hh[(size_t)E * T * DFF];
__device__ float  g_Y[SPLITK][E * T * D];

__global__ void reset_kernel() {
    if (threadIdx.x < E) g_cnt[threadIdx.x] = 0;
    if (threadIdx.x < E * SPLITK) g_done[threadIdx.x] = 0;
    if (threadIdx.x == 32) g_q = 0;
    if (threadIdx.x == 33) g_aux1 = 0;
    if (threadIdx.x == 34) g_aux2 = 0;
    if (threadIdx.x == 35) g_g2 = 0;
}

// ---------------------------------------------------------------------------
// helpers
// ---------------------------------------------------------------------------
__device__ __forceinline__ uint4 pack8(float4 a, float4 b) {
    __half2 h0 = __floats2half2_rn(a.x, a.y);
    __half2 h1 = __floats2half2_rn(a.z, a.w);
    __half2 h2 = __floats2half2_rn(b.x, b.y);
    __half2 h3 = __floats2half2_rn(b.z, b.w);
    uint4 u;
    u.x = *reinterpret_cast<uint32_t*>(&h0);
    u.y = *reinterpret_cast<uint32_t*>(&h1);
    u.z = *reinterpret_cast<uint32_t*>(&h2);
    u.w = *reinterpret_cast<uint32_t*>(&h3);
    return u;
}
__device__ __forceinline__ uint32_t smem_u32(const void* p) {
    return (uint32_t)__cvta_generic_to_shared(p);
}
__device__ __forceinline__ void cp16(uint32_t dst, const void* src) {
    asm volatile("cp.async.cg.shared.global [%0], [%1], 16;"
                 :: "r"(dst), "l"(src) : "memory");
}
__device__ __forceinline__ void cp_commit() {
    asm volatile("cp.async.commit_group;" ::: "memory");
}
template <int N>
__device__ __forceinline__ void cp_wait() {
    asm volatile("cp.async.wait_group %0;" :: "n"(N) : "memory");
}
__device__ __forceinline__ void ldsm4(uint32_t& r0, uint32_t& r1, uint32_t& r2, uint32_t& r3,
                                      uint32_t addr) {
    asm volatile("ldmatrix.sync.aligned.m8n8.x4.shared.b16 {%0,%1,%2,%3}, [%4];"
                 : "=r"(r0), "=r"(r1), "=r"(r2), "=r"(r3) : "r"(addr));
}
__device__ __forceinline__ void mma_f16(float& c0, float& c1, float& c2, float& c3,
                                        uint32_t a0, uint32_t a1, uint32_t a2, uint32_t a3,
                                        uint32_t b0, uint32_t b1) {
    asm volatile(
        "mma.sync.aligned.m16n8k16.row.col.f32.f16.f16.f32 "
        "{%0,%1,%2,%3}, {%4,%5,%6,%7}, {%8,%9}, {%0,%1,%2,%3};"
        : "+f"(c0), "+f"(c1), "+f"(c2), "+f"(c3)
        : "r"(a0), "r"(a1), "r"(a2), "r"(a3), "r"(b0), "r"(b1));
}

__device__ __forceinline__ void load_frags(uint32_t (&af)[4][4], uint32_t (&bf)[8][2],
                                           const uint32_t (&aAddr)[4],
                                           const uint32_t (&bAddr)[4], uint32_t off)
{
    #pragma unroll
    for (int mi = 0; mi < 4; mi++)
        ldsm4(af[mi][0], af[mi][1], af[mi][2], af[mi][3], aAddr[mi] + off);
    #pragma unroll
    for (int p = 0; p < 4; p++) {
        uint32_t r0, r1, r2, r3;
        ldsm4(r0, r1, r2, r3, bAddr[p] + off);
        bf[2 * p][0] = r0;     bf[2 * p][1] = r1;
        bf[2 * p + 1][0] = r2; bf[2 * p + 1][1] = r3;
    }
}

__device__ __forceinline__ void mma_tile(float (&acc)[4][8][4],
                                         const uint32_t (&af)[4][4],
                                         const uint32_t (&bf)[8][2])
{
    #pragma unroll
    for (int mi = 0; mi < 4; mi++)
        #pragma unroll
        for (int ni = 0; ni < 8; ni++)
            mma_f16(acc[mi][ni][0], acc[mi][ni][1], acc[mi][ni][2], acc[mi][ni][3],
                    af[mi][0], af[mi][1], af[mi][2], af[mi][3],
                    bf[ni][0], bf[ni][1]);
}

// ---------------------------------------------------------------------------
// Router body: one warp per token, noisy top-2 gating + atomic per-expert
// compaction. Row values position-invariant -> deterministic output.
// ---------------------------------------------------------------------------
__device__ void router_body(int tok, int lane,
                            const float* __restrict__ x,
                            const float* __restrict__ noise,
                            const float* __restrict__ Wg,
                            const float* __restrict__ bg,
                            const float* __restrict__ Wn,
                            const float* __restrict__ bn)
{
    const float* xr = x + (size_t)tok * D;
    float xv[D / 32];
    #pragma unroll
    for (int i = 0; i < D / 32; i++) xv[i] = xr[lane + 32 * i];

    float nz[E];
    #pragma unroll
    for (int e = 0; e < E; e++) {
        const float* g  = Wg + e * D;
        const float* nw = Wn + e * D;
        float s1 = 0.f, s2 = 0.f;
        #pragma unroll
        for (int i = 0; i < D / 32; i++) {
            const float xi = xv[i];
            s1 = fmaf(xi, g[lane + 32 * i], s1);
            s2 = fmaf(xi, nw[lane + 32 * i], s2);
        }
        #pragma unroll
        for (int off = 16; off; off >>= 1) {
            s1 += __shfl_xor_sync(0xffffffffu, s1, off);
            s2 += __shfl_xor_sync(0xffffffffu, s2, off);
        }
        const float logit = s1 + bg[e];
        const float nlog  = s2 + bn[e];
        const float sp = fmaxf(nlog, 0.f) + log1pf(expf(-fabsf(nlog)));
        nz[e] = logit + noise[tok * E + e] * sp;
    }

    if (lane == 0) {
        int i0 = 0; float v0 = nz[0];
        #pragma unroll
        for (int e = 1; e < E; e++) if (nz[e] > v0) { v0 = nz[e]; i0 = e; }
        int i1 = -1; float v1 = -3.0e38f;
        #pragma unroll
        for (int e = 0; e < E; e++) if (e != i0 && nz[e] > v1) { v1 = nz[e]; i1 = e; }

        const float ex = expf(v1 - v0);
        const float inv = 1.f / (1.f + ex);

        const int p0 = atomicAdd(&g_cnt[i0], 1);
        const int p1 = atomicAdd(&g_cnt[i1], 1);
        const int r0 = i0 * T + p0;
        const int r1 = i1 * T + p1;
        g_tok[r0] = tok;
        g_tok[r1] = tok;
        g_rowof[2 * tok]     = r0;
        g_rowof[2 * tok + 1] = r1;
        g_w[2 * tok]     = inv;
        g_w[2 * tok + 1] = ex * inv;
    }
}

// cvt helper: nb batches of 8 chunks (8 elems each) per thread
__device__ __forceinline__ void cvt_batches(const float* __restrict__ src,
                                            __half* __restrict__ dst,
                                            int base, int tid, int nb)
{
    for (int bt = 0; bt < nb; bt++) {
        const int ci = base + bt * 2048 + tid;
        float4 va[8], vb[8];
        #pragma unroll
        for (int u = 0; u < 8; u++) {
            va[u] = reinterpret_cast<const float4*>(src)[(size_t)2 * (ci + 256 * u)];
            vb[u] = reinterpret_cast<const float4*>(src)[(size_t)2 * (ci + 256 * u) + 1];
        }
        #pragma unroll
        for (int u = 0; u < 8; u++)
            reinterpret_cast<uint4*>(dst)[ci + 256 * u] = pack8(va[u], vb[u]);
    }
}

// ---------------------------------------------------------------------------
// Mega persistent kernel: cvt + router + GEMM1 + GEMM2 + combine.
// Queue order == dependency order; producers never wait on later items =>
// deadlock-free. All values are pure functions of item id => deterministic.
// ---------------------------------------------------------------------------
__global__ __launch_bounds__(256, 1)
void moe_mega(const float* __restrict__ x,
              const float* __restrict__ noise,
              const float* __restrict__ Wg,
              const float* __restrict__ bg,
              const float* __restrict__ Wn,
              const float* __restrict__ bn,
              const float* __restrict__ W1,
              const float* __restrict__ b1,
              const float* __restrict__ W2,
              const float* __restrict__ b2,
              float* __restrict__ out)
{
    extern __shared__ __half sm[];
    __shared__ int s_t;

    const int tid  = threadIdx.x;
    const int lane = tid & 31;
    const int warp = tid >> 5;
    const int wm   = warp >> 2;
    const int wn   = warp & 3;
    const int g    = lane >> 2;
    const int q    = lane & 3;

    const int r8 = tid >> 3;
    const int c8 = (tid & 7) * 8;
    const uint32_t smb = smem_u32(sm);
    const uint32_t st0 = smb + (uint32_t)(r8 * SA + c8) * 2;

    uint32_t aAddr[4], bAddr[4];
    {
        const int rin = lane & 15;
        const int ch  = lane >> 4;
        #pragma unroll
        for (int mi = 0; mi < 4; mi++)
            aAddr[mi] = smb + (uint32_t)((wm * 64 + mi * 16 + rin) * SA + ch * 8) * 2;
    }
    {
        const int rin = ((lane >> 4) << 3) + (lane & 7);
        const int ch  = (lane >> 3) & 1;
        #pragma unroll
        for (int p = 0; p < 4; p++)
            bAddr[p] = smb + (uint32_t)((BM + wn * 64 + p * 16 + rin) * SA + ch * 8) * 2;
    }

    int rdy1 = 0, rdy2 = 0, rdyCB = 0;   // per-CTA dep caches (tid0 only)

    for (;;) {
        if (tid == 0) s_t = atomicAdd(&g_q, 1);
        __syncthreads();
        const int t = s_t;
        __syncthreads();
        if (t >= NTOT_Q) break;

        // ================= AUX items =================
        if (t < OG1) {
            if (t < OB) {                       // cvt x: 6144 chunks = 3 batches
                cvt_batches(x, g_xh, t * 6144, tid, 3);
            } else if (t < OC) {                // router: 8 tokens
                router_body((t - OB) * 8 + warp, lane, x, noise, Wg, bg, Wn, bn);
            } else if (t < OD) {                // cvt W1: 12288 chunks = 6 batches
                cvt_batches(W1, g_W1h, (t - OC) * 12288, tid, 6);
            } else {                            // cvt W2
                cvt_batches(W2, g_W2h, (t - OD) * 12288, tid, 6);
            }
            __threadfence();
            __syncthreads();
            if (tid == 0) atomicAdd((t < OD) ? &g_aux1 : &g_aux2, 1);
            continue;
        }

        // ================= combine items =================
        if (t >= OCB) {
            if (tid == 0 && !rdyCB) {
                while (atomicAdd(&g_g2, 0) < NG2) __nanosleep(128);
                rdyCB = 1;
            }
            __syncthreads();
            __threadfence();
            const int k   = t - OCB;
            const int tok = k * 32 + (tid >> 3);
            const int j0  = tid & 7;
            const int r0 = g_rowof[2 * tok];
            const int r1 = g_rowof[2 * tok + 1];
            const float w0 = g_w[2 * tok];
            const float w1 = g_w[2 * tok + 1];
            for (int it = 0; it < 24; it++) {
                const int f4 = 8 * it + j0;
                float4 sa = make_float4(0.f, 0.f, 0.f, 0.f);
                float4 sb = make_float4(0.f, 0.f, 0.f, 0.f);
                #pragma unroll
                for (int s = 0; s < SPLITK; s++) {
                    const float4 a = reinterpret_cast<const float4*>(g_Y[s] + (size_t)r0 * D)[f4];
                    const float4 b = reinterpret_cast<const float4*>(g_Y[s] + (size_t)r1 * D)[f4];
                    sa.x += a.x; sa.y += a.y; sa.z += a.z; sa.w += a.w;
                    sb.x += b.x; sb.y += b.y; sb.z += b.z; sb.w += b.w;
                }
                float4 o;
                o.x = fmaf(w0, sa.x, w1 * sb.x);
                o.y = fmaf(w0, sa.y, w1 * sb.y);
                o.z = fmaf(w0, sa.z, w1 * sb.z);
                o.w = fmaf(w0, sa.w, w1 * sb.w);
                reinterpret_cast<float4*>(out + (size_t)tok * D)[f4] = o;
            }
            continue;
        }

        // ================= GEMM items =================
        const bool m1 = (t < OG2);
        int xi, yi, e, sK;
        if (m1) {
            const int i = t - OG1;
            xi = i % 12; yi = (i / 12) & 15; e = i / 192; sK = 0;
        } else {
            const int j = t - OG2;
            xi = j % 3; yi = (j / 3) & 15;
            const int zi = j / 48;
            e = zi & (E - 1); sK = zi >> 3;
        }

        // dependency waits (BEFORE reading g_cnt)
        if (tid == 0) {
            if (m1) {
                if (!rdy1) {
                    while (atomicAdd(&g_aux1, 0) < AUX1_TGT) __nanosleep(128);
                    rdy1 = 1;
                }
            } else {
                if (!rdy2) {
                    while (atomicAdd(&g_aux2, 0) < AUX2_TGT) __nanosleep(128);
                    rdy2 = 1;
                }
                while (atomicAdd(&g_done[e * SPLITK + sK], 0) < DEP_TARGET)
                    __nanosleep(128);
            }
        }
        __syncthreads();
        __threadfence();

        const int cnt = g_cnt[e];
        const int m0  = yi * BM;
        if (m0 >= cnt) {
            if (tid == 0) {
                if (m1) atomicAdd(&g_done[e * SPLITK + xi / 3], 1);
                else    atomicAdd(&g_g2, 1);
            }
            continue;
        }
        const int n0 = xi * BN;
        const int KROW = m1 ? D : DFF;
        const int NTOT = m1 ? DFF : D;
        const int ks0  = m1 ? 0 : sK * (DFF / SPLITK);

        const __half* srcA[4];
        #pragma unroll
        for (int k = 0; k < 4; k++) {
            const int am = m0 + r8 + 32 * k;
            if (m1) {
                const int tok = (am < cnt) ? g_tok[e * T + am] : 0;
                srcA[k] = g_xh + (size_t)tok * D + c8;
            } else {
                const int r = (am < cnt) ? am : 0;
                srcA[k] = g_Hh + ((size_t)e * T + r) * DFF + ks0 + c8;
            }
        }
        const __half* Wh = m1 ? g_W1h : g_W2h;
        const __half* srcB = Wh + ((size_t)e * NTOT + n0 + r8) * KROW + ks0 + c8;
        const size_t bstep = (size_t)32 * KROW;

        float acc[4][8][4];
        #pragma unroll
        for (int mi = 0; mi < 4; mi++)
            #pragma unroll
            for (int ni = 0; ni < 8; ni++)
                #pragma unroll
                for (int r = 0; r < 4; r++) acc[mi][ni][r] = 0.f;

        auto FILL = [&](int stage, int kt) {
            const uint32_t so = (uint32_t)(stage * STG_BYTES);
            const int ko = kt * BK;
            #pragma unroll
            for (int k = 0; k < 4; k++)
                cp16(st0 + so + k * (32 * SA * 2), srcA[k] + ko);
            #pragma unroll
            for (int k = 0; k < 8; k++)
                cp16(st0 + so + (k + 4) * (32 * SA * 2), srcB + bstep * k + ko);
        };

        #pragma unroll
        for (int s = 0; s < STAGES - 1; s++) { FILL(s, s); cp_commit(); }
        cp_wait<1>();
        __syncthreads();

        uint32_t af0[4][4], bf0[8][2], af1[4][4], bf1[8][2];
        load_frags(af0, bf0, aAddr, bAddr, 0);

        int cur = 0;
        for (int kt = 0; kt < NKT; kt++) {
            const uint32_t soff = (uint32_t)(cur * STG_BYTES);

            load_frags(af1, bf1, aAddr, bAddr, soff + 32);
            if (kt + STAGES - 1 < NKT) {
                int tgt = cur + 2; if (tgt >= STAGES) tgt -= STAGES;
                FILL(tgt, kt + STAGES - 1);
            }
            cp_commit();
            mma_tile(acc, af0, bf0);                       // sub0

            load_frags(af0, bf0, aAddr, bAddr, soff + 64); // sub2 frags
            mma_tile(acc, af1, bf1);                       // sub1

            load_frags(af1, bf1, aAddr, bAddr, soff + 96); // sub3 frags
            mma_tile(acc, af0, bf0);                       // sub2

            cp_wait<1>();
            __syncthreads();

            int nxt = cur + 1; if (nxt >= STAGES) nxt = 0;
            if (kt + 1 < NKT)
                load_frags(af0, bf0, aAddr, bAddr, (uint32_t)(nxt * STG_BYTES));
            mma_tile(acc, af1, bf1);                       // sub3

            cur = nxt;
        }

        // ---- epilogue ----
        if (m1) {
            const float* be = b1 + (size_t)e * DFF;
            __half* Cb = g_Hh + (size_t)e * T * DFF;
            #pragma unroll
            for (int mi = 0; mi < 4; mi++) {
                #pragma unroll
                for (int hh = 0; hh < 2; hh++) {
                    const int m = m0 + wm * 64 + mi * 16 + g + hh * 8;
                    if (m < cnt) {
                        __half* cr = Cb + (size_t)m * DFF;
                        #pragma unroll
                        for (int ni = 0; ni < 8; ni++) {
                            const int c = n0 + wn * 64 + ni * 8 + 2 * q;
                            float v0 = acc[mi][ni][2 * hh]     + be[c];
                            float v1 = acc[mi][ni][2 * hh + 1] + be[c + 1];
                            v0 = fmaxf(v0, 0.f); v1 = fmaxf(v1, 0.f);
                            *reinterpret_cast<__half2*>(cr + c) = __floats2half2_rn(v0, v1);
                        }
                    }
                }
            }
            __threadfence();
            __syncthreads();
            if (tid == 0) atomicAdd(&g_done[e * SPLITK + xi / 3], 1);
        } else {
            const float* be = b2 + (size_t)e * D;
            float* Cb = g_Y[sK] + (size_t)e * T * D;
            #pragma unroll
            for (int mi = 0; mi < 4; mi++) {
                #pragma unroll
                for (int hh = 0; hh < 2; hh++) {
                    const int m = m0 + wm * 64 + mi * 16 + g + hh * 8;
                    if (m < cnt) {
                        float* cr = Cb + (size_t)m * D;
                        #pragma unroll
                        for (int ni = 0; ni < 8; ni++) {
                            const int c = n0 + wn * 64 + ni * 8 + 2 * q;
                            float v0 = acc[mi][ni][2 * hh];
                            float v1 = acc[mi][ni][2 * hh + 1];
                            if (sK == 0) { v0 += be[c]; v1 += be[c + 1]; }
                            *reinterpret_cast<float2*>(cr + c) = make_float2(v0, v1);
                        }
                    }
                }
            }
            __threadfence();
            __syncthreads();
            if (tid == 0) atomicAdd(&g_g2, 1);
        }
    }
}

// ---------------------------------------------------------------------------
// Launch
// ---------------------------------------------------------------------------
extern "C" void kernel_launch(void* const* d_in, const int* in_sizes, int n_in,
                              void* d_out, int out_size)
{
    const float* x     = (const float*)d_in[0];
    const float* noise = (const float*)d_in[1];
    const float* Wg    = (const float*)d_in[2];
    const float* bg    = (const float*)d_in[3];
    const float* Wn    = (const float*)d_in[4];
    const float* bn    = (const float*)d_in[5];
    const float* W1    = (const float*)d_in[6];
    const float* b1    = (const float*)d_in[7];
    const float* W2    = (const float*)d_in[8];
    const float* b2    = (const float*)d_in[9];
    float* out = (float*)d_out;

    cudaFuncSetAttribute(moe_mega,
                         cudaFuncAttributeMaxDynamicSharedMemorySize, SMEM_TOT);

    reset_kernel<<<1, 64>>>();
    moe_mega<<<NSM, 256, SMEM_TOT>>>(x, noise, Wg, bg, Wn, bn, W1, b1, W2, b2, out);
}

// round 16
// speedup vs baseline: 1.1532x; 1.1532x over previous
#include <cuda_runtime.h>
#include <cuda_fp16.h>
#include <math.h>
#include <stdint.h>

// Problem constants: B=2, S=1024 -> T=2048 tokens; D=768; E=8 experts; DFF=3072; top-2.
#define T    2048
#define D    768
#define E    8
#define DFF  3072

// GEMM tiling (R10 best-measured config): 128x256 CTA tile, 256 threads
// (8 warps, 2x4), 64x64 warp tiles, BK=64 (4 sub-k16 per sync), fp16 mma.sync
// + ldmatrix, 3-stage cp.async, software-pipelined fragments.
// NEW vs R10: aux kernels overlap via forked streams (router || cvt; cvt-W2
// hidden under router/GEMM1). GEMM/math kernels are byte-identical to R10.
#define BM 128
#define BN 256
#define BK 64
#define SA 72                       // smem row stride (halves): 64 + 8 pad
#define STAGES 3
#define STG_ROWS (BM + BN)          // 384 rows (A then B) per stage
#define STG_BYTES (STG_ROWS * SA * 2)   // 55296 B per stage
#define SMEM_TOT (STAGES * STG_BYTES)   // 165888 B
#define SPLITK 4

// ---------------------------------------------------------------------------
// Device scratch
// ---------------------------------------------------------------------------
__device__ int    g_cnt[E];
__device__ int    g_tok[E * T];
__device__ int    g_rowof[T * 2];
__device__ float  g_w[T * 2];
__device__ __half g_xh[T * D];                    // x in fp16
__device__ __half g_W1h[(size_t)E * DFF * D];     // W1 in fp16
__device__ __half g_W2h[(size_t)E * D * DFF];     // W2 in fp16
__device__ __half g_Hh[(size_t)E * T * DFF];      // hidden acts, fp16
__device__ float  g_Y[SPLITK][E * T * D];         // split-K partial outputs

__global__ void reset_kernel() {
    if (threadIdx.x < E) g_cnt[threadIdx.x] = 0;
}

// ---------------------------------------------------------------------------
// fp32 -> fp16 conversion kernels (8 elems / thread)
// ---------------------------------------------------------------------------
__device__ __forceinline__ uint4 pack8(float4 a, float4 b) {
    __half2 h0 = __floats2half2_rn(a.x, a.y);
    __half2 h1 = __floats2half2_rn(a.z, a.w);
    __half2 h2 = __floats2half2_rn(b.x, b.y);
    __half2 h3 = __floats2half2_rn(b.z, b.w);
    uint4 u;
    u.x = *reinterpret_cast<uint32_t*>(&h0);
    u.y = *reinterpret_cast<uint32_t*>(&h1);
    u.z = *reinterpret_cast<uint32_t*>(&h2);
    u.w = *reinterpret_cast<uint32_t*>(&h3);
    return u;
}

// two-source cvt: x then W1
__global__ void cvt2_kernel(const float* __restrict__ x,
                            const float* __restrict__ W1,
                            __half* __restrict__ xh,
                            __half* __restrict__ w1h,
                            int nx8, int nw8)
{
    const int i = blockIdx.x * blockDim.x + threadIdx.x;
    const float* src; __half* dst; int j;
    if (i < nx8)            { src = x;  dst = xh;  j = i; }
    else if (i < nx8 + nw8) { src = W1; dst = w1h; j = i - nx8; }
    else return;
    const float4 a = reinterpret_cast<const float4*>(src)[2 * j];
    const float4 b = reinterpret_cast<const float4*>(src)[2 * j + 1];
    reinterpret_cast<uint4*>(dst)[j] = pack8(a, b);
}

// single-source cvt: W2
__global__ void cvt1_kernel(const float* __restrict__ W2,
                            __half* __restrict__ w2h, int n8)
{
    const int i = blockIdx.x * blockDim.x + threadIdx.x;
    if (i >= n8) return;
    const float4 a = reinterpret_cast<const float4*>(W2)[2 * i];
    const float4 b = reinterpret_cast<const float4*>(W2)[2 * i + 1];
    reinterpret_cast<uint4*>(w2h)[i] = pack8(a, b);
}

// ---------------------------------------------------------------------------
// Router: one warp per token, noisy top-2 gating + atomic per-expert
// compaction. Row values are position-invariant -> deterministic output.
// ---------------------------------------------------------------------------
__global__ void router_kernel(const float* __restrict__ x,
                              const float* __restrict__ noise,
                              const float* __restrict__ Wg,
                              const float* __restrict__ bg,
                              const float* __restrict__ Wn,
                              const float* __restrict__ bn)
{
    const int warp = (blockIdx.x * blockDim.x + threadIdx.x) >> 5;
    const int lane = threadIdx.x & 31;
    if (warp >= T) return;

    const float* xr = x + (size_t)warp * D;
    float xv[D / 32];
    #pragma unroll
    for (int i = 0; i < D / 32; i++) xv[i] = xr[lane + 32 * i];

    float nz[E];
    #pragma unroll
    for (int e = 0; e < E; e++) {
        const float* g  = Wg + e * D;
        const float* nw = Wn + e * D;
        float s1 = 0.f, s2 = 0.f;
        #pragma unroll
        for (int i = 0; i < D / 32; i++) {
            const float xi = xv[i];
            s1 = fmaf(xi, g[lane + 32 * i], s1);
            s2 = fmaf(xi, nw[lane + 32 * i], s2);
        }
        #pragma unroll
        for (int off = 16; off; off >>= 1) {
            s1 += __shfl_xor_sync(0xffffffffu, s1, off);
            s2 += __shfl_xor_sync(0xffffffffu, s2, off);
        }
        const float logit = s1 + bg[e];
        const float nlog  = s2 + bn[e];
        const float sp = fmaxf(nlog, 0.f) + log1pf(expf(-fabsf(nlog)));
        nz[e] = logit + noise[warp * E + e] * sp;
    }

    if (lane == 0) {
        int i0 = 0; float v0 = nz[0];
        #pragma unroll
        for (int e = 1; e < E; e++) if (nz[e] > v0) { v0 = nz[e]; i0 = e; }
        int i1 = -1; float v1 = -3.0e38f;
        #pragma unroll
        for (int e = 0; e < E; e++) if (e != i0 && nz[e] > v1) { v1 = nz[e]; i1 = e; }

        const float ex = expf(v1 - v0);
        const float inv = 1.f / (1.f + ex);

        const int p0 = atomicAdd(&g_cnt[i0], 1);
        const int p1 = atomicAdd(&g_cnt[i1], 1);
        const int r0 = i0 * T + p0;
        const int r1 = i1 * T + p1;
        g_tok[r0] = warp;
        g_tok[r1] = warp;
        g_rowof[2 * warp]     = r0;
        g_rowof[2 * warp + 1] = r1;
        g_w[2 * warp]     = inv;
        g_w[2 * warp + 1] = ex * inv;
    }
}

// ---------------------------------------------------------------------------
// helpers
// ---------------------------------------------------------------------------
__device__ __forceinline__ uint32_t smem_u32(const void* p) {
    return (uint32_t)__cvta_generic_to_shared(p);
}
__device__ __forceinline__ void cp16(uint32_t dst, const void* src) {
    asm volatile("cp.async.cg.shared.global [%0], [%1], 16;"
                 :: "r"(dst), "l"(src) : "memory");
}
__device__ __forceinline__ void cp_commit() {
    asm volatile("cp.async.commit_group;" ::: "memory");
}
template <int N>
__device__ __forceinline__ void cp_wait() {
    asm volatile("cp.async.wait_group %0;" :: "n"(N) : "memory");
}
__device__ __forceinline__ void ldsm4(uint32_t& r0, uint32_t& r1, uint32_t& r2, uint32_t& r3,
                                      uint32_t addr) {
    asm volatile("ldmatrix.sync.aligned.m8n8.x4.shared.b16 {%0,%1,%2,%3}, [%4];"
                 : "=r"(r0), "=r"(r1), "=r"(r2), "=r"(r3) : "r"(addr));
}
__device__ __forceinline__ void mma_f16(float& c0, float& c1, float& c2, float& c3,
                                        uint32_t a0, uint32_t a1, uint32_t a2, uint32_t a3,
                                        uint32_t b0, uint32_t b1) {
    asm volatile(
        "mma.sync.aligned.m16n8k16.row.col.f32.f16.f16.f32 "
        "{%0,%1,%2,%3}, {%4,%5,%6,%7}, {%8,%9}, {%0,%1,%2,%3};"
        : "+f"(c0), "+f"(c1), "+f"(c2), "+f"(c3)
        : "r"(a0), "r"(a1), "r"(a2), "r"(a3), "r"(b0), "r"(b1));
}

// load one sub-k16 fragment set (A: 4 x ldsm.x4, B: 4 x ldsm.x4)
__device__ __forceinline__ void load_frags(uint32_t (&af)[4][4], uint32_t (&bf)[8][2],
                                           const uint32_t (&aAddr)[4],
                                           const uint32_t (&bAddr)[4], uint32_t off)
{
    #pragma unroll
    for (int mi = 0; mi < 4; mi++)
        ldsm4(af[mi][0], af[mi][1], af[mi][2], af[mi][3], aAddr[mi] + off);
    #pragma unroll
    for (int p = 0; p < 4; p++) {
        uint32_t r0, r1, r2, r3;
        ldsm4(r0, r1, r2, r3, bAddr[p] + off);
        bf[2 * p][0] = r0;     bf[2 * p][1] = r1;
        bf[2 * p + 1][0] = r2; bf[2 * p + 1][1] = r3;
    }
}

// 4x8 grid of m16n8k16 MMAs for one sub-k16
__device__ __forceinline__ void mma_tile(float (&acc)[4][8][4],
                                         const uint32_t (&af)[4][4],
                                         const uint32_t (&bf)[8][2])
{
    #pragma unroll
    for (int mi = 0; mi < 4; mi++)
        #pragma unroll
        for (int ni = 0; ni < 8; ni++)
            mma_f16(acc[mi][ni][0], acc[mi][ni][1], acc[mi][ni][2], acc[mi][ni][3],
                    af[mi][0], af[mi][1], af[mi][2], af[mi][3],
                    bf[ni][0], bf[ni][1]);
}

// ---------------------------------------------------------------------------
// Grouped fp16 tensor-core GEMM (identical to R10). 128x256 tile, 64x64 warp
// tiles, BK=64 (4 sub-k16 per sync), 3-stage cp.async, pipelined fragments.
//   MODE 0: H = relu(gather(xh) @ W1h[e]^T + b1);   K=768,  N=3072, out fp16
//   MODE 1: Y = Hh @ W2h[e]^T (+b2 on split 0);     K=768/split x4, N=768, fp32
// ---------------------------------------------------------------------------
template <int MODE>
__global__ __launch_bounds__(256, 1)
void gemm_f16_kernel(const __half* __restrict__ Wh,
                     const float* __restrict__ bias)
{
    constexpr int KROW = (MODE == 0) ? D : DFF;      // row stride of A and W
    constexpr int NTOT = (MODE == 0) ? DFF : D;
    constexpr int KLEN = (MODE == 0) ? D : (DFF / SPLITK);
    constexpr int NKT  = KLEN / BK;

    extern __shared__ __half sm[];

    int e, sK;
    if (MODE == 0) { e = blockIdx.z; sK = 0; }
    else           { e = blockIdx.z & (E - 1); sK = blockIdx.z >> 3; }
    const int ks0 = (MODE == 1) ? sK * KLEN : 0;

    const int cnt = g_cnt[e];
    const int m0  = blockIdx.y * BM;
    if (m0 >= cnt) return;
    const int n0  = blockIdx.x * BN;

    const int tid  = threadIdx.x;
    const int lane = tid & 31;
    const int warp = tid >> 5;
    const int wm   = warp >> 2;        // 0..1  (64-row slices)
    const int wn   = warp & 3;         // 0..3  (64-col slices)
    const int g    = lane >> 2;
    const int q    = lane & 3;

    // ---- staging: 384 rows x 64 halves = 3072 16B-chunks; 12 per thread.
    const int r8 = tid >> 3;
    const int c8 = (tid & 7) * 8;
    const uint32_t smb = smem_u32(sm);
    const uint32_t st0 = smb + (uint32_t)(r8 * SA + c8) * 2;

    const __half* srcA[4];
    #pragma unroll
    for (int k = 0; k < 4; k++) {
        const int am = m0 + r8 + 32 * k;
        if (MODE == 0) {
            const int tok = (am < cnt) ? g_tok[e * T + am] : 0;
            srcA[k] = g_xh + (size_t)tok * KROW + c8;
        } else {
            const int r = (am < cnt) ? am : 0;
            srcA[k] = g_Hh + ((size_t)e * T + r) * KROW + ks0 + c8;
        }
    }
    const __half* srcB = Wh + ((size_t)e * NTOT + n0 + r8) * KROW + ks0 + c8;

    uint32_t aAddr[4], bAddr[4];
    {
        const int rin = lane & 15;
        const int ch  = lane >> 4;
        #pragma unroll
        for (int mi = 0; mi < 4; mi++)
            aAddr[mi] = smb + (uint32_t)((wm * 64 + mi * 16 + rin) * SA + ch * 8) * 2;
    }
    {
        const int rin = ((lane >> 4) << 3) + (lane & 7);
        const int ch  = (lane >> 3) & 1;
        #pragma unroll
        for (int p = 0; p < 4; p++)
            bAddr[p] = smb + (uint32_t)((BM + wn * 64 + p * 16 + rin) * SA + ch * 8) * 2;
    }

    float acc[4][8][4];
    #pragma unroll
    for (int mi = 0; mi < 4; mi++)
        #pragma unroll
        for (int ni = 0; ni < 8; ni++)
            #pragma unroll
            for (int r = 0; r < 4; r++) acc[mi][ni][r] = 0.f;

    auto FILL = [&](int stage, int kt) {
        const uint32_t so = (uint32_t)(stage * STG_BYTES);
        const int ko = kt * BK;
        #pragma unroll
        for (int k = 0; k < 4; k++)
            cp16(st0 + so + k * (32 * SA * 2), srcA[k] + ko);
        #pragma unroll
        for (int k = 0; k < 8; k++)
            cp16(st0 + so + (k + 4) * (32 * SA * 2), srcB + (size_t)(32 * k) * KROW + ko);
    };

    // prologue: fill stages 0..1
    #pragma unroll
    for (int s = 0; s < STAGES - 1; s++) { FILL(s, s); cp_commit(); }
    cp_wait<1>();
    __syncthreads();

    uint32_t af0[4][4], bf0[8][2], af1[4][4], bf1[8][2];
    load_frags(af0, bf0, aAddr, bAddr, 0);

    int cur = 0;
    for (int kt = 0; kt < NKT; kt++) {
        const uint32_t soff = (uint32_t)(cur * STG_BYTES);

        load_frags(af1, bf1, aAddr, bAddr, soff + 32);
        if (kt + STAGES - 1 < NKT) {
            int tgt = cur + 2; if (tgt >= STAGES) tgt -= STAGES;
            FILL(tgt, kt + STAGES - 1);
        }
        cp_commit();
        mma_tile(acc, af0, bf0);                       // sub0

        load_frags(af0, bf0, aAddr, bAddr, soff + 64); // sub2 frags
        mma_tile(acc, af1, bf1);                       // sub1

        load_frags(af1, bf1, aAddr, bAddr, soff + 96); // sub3 frags
        mma_tile(acc, af0, bf0);                       // sub2

        cp_wait<1>();
        __syncthreads();

        int nxt = cur + 1; if (nxt >= STAGES) nxt = 0;
        if (kt + 1 < NKT)
            load_frags(af0, bf0, aAddr, bAddr, (uint32_t)(nxt * STG_BYTES));
        mma_tile(acc, af1, bf1);                       // sub3

        cur = nxt;
    }

    // ---- epilogue ----
    const float* be = bias + (size_t)e * NTOT;
    if (MODE == 0) {
        __half* Cb = g_Hh + (size_t)e * T * NTOT;
        #pragma unroll
        for (int mi = 0; mi < 4; mi++) {
            #pragma unroll
            for (int hh = 0; hh < 2; hh++) {
                const int m = m0 + wm * 64 + mi * 16 + g + hh * 8;
                if (m < cnt) {
                    __half* cr = Cb + (size_t)m * NTOT;
                    #pragma unroll
                    for (int ni = 0; ni < 8; ni++) {
                        const int c = n0 + wn * 64 + ni * 8 + 2 * q;
                        float v0 = acc[mi][ni][2 * hh]     + be[c];
                        float v1 = acc[mi][ni][2 * hh + 1] + be[c + 1];
                        v0 = fmaxf(v0, 0.f); v1 = fmaxf(v1, 0.f);
                        *reinterpret_cast<__half2*>(cr + c) = __floats2half2_rn(v0, v1);
                    }
                }
            }
        }
    } else {
        float* Cb = g_Y[sK] + (size_t)e * T * NTOT;
        #pragma unroll
        for (int mi = 0; mi < 4; mi++) {
            #pragma unroll
            for (int hh = 0; hh < 2; hh++) {
                const int m = m0 + wm * 64 + mi * 16 + g + hh * 8;
                if (m < cnt) {
                    float* cr = Cb + (size_t)m * NTOT;
                    #pragma unroll
                    for (int ni = 0; ni < 8; ni++) {
                        const int c = n0 + wn * 64 + ni * 8 + 2 * q;
                        float v0 = acc[mi][ni][2 * hh];
                        float v1 = acc[mi][ni][2 * hh + 1];
                        if (sK == 0) { v0 += be[c]; v1 += be[c + 1]; }
                        *reinterpret_cast<float2*>(cr + c) = make_float2(v0, v1);
                    }
                }
            }
        }
    }
}

// ---------------------------------------------------------------------------
// Combine (deterministic): out[t] = w0*sum_s Ys[r0] + w1*sum_s Ys[r1]
// ---------------------------------------------------------------------------
__global__ void combine_kernel(float* __restrict__ out)
{
    const int t = blockIdx.x;
    const int j = threadIdx.x;            // 0..191
    const int r0 = g_rowof[2 * t];
    const int r1 = g_rowof[2 * t + 1];
    const float w0 = g_w[2 * t];
    const float w1 = g_w[2 * t + 1];
    float4 sa = make_float4(0.f, 0.f, 0.f, 0.f);
    float4 sb = make_float4(0.f, 0.f, 0.f, 0.f);
    #pragma unroll
    for (int s = 0; s < SPLITK; s++) {
        const float4 a = reinterpret_cast<const float4*>(g_Y[s] + (size_t)r0 * D)[j];
        const float4 b = reinterpret_cast<const float4*>(g_Y[s] + (size_t)r1 * D)[j];
        sa.x += a.x; sa.y += a.y; sa.z += a.z; sa.w += a.w;
        sb.x += b.x; sb.y += b.y; sb.z += b.z; sb.w += b.w;
    }
    float4 o;
    o.x = fmaf(w0, sa.x, w1 * sb.x);
    o.y = fmaf(w0, sa.y, w1 * sb.y);
    o.z = fmaf(w0, sa.z, w1 * sb.z);
    o.w = fmaf(w0, sa.w, w1 * sb.w);
    reinterpret_cast<float4*>(out + (size_t)t * D)[j] = o;
}

// ---------------------------------------------------------------------------
// Launch: fork/join streams for aux concurrency (graph-capturable pattern).
//   s0 (default): reset -> cvt(x,W1) -> [wait router] GEMM1 -> [wait W2] GEMM2
//                 -> combine
//   s1: [wait reset] router
//   s2: [wait reset] cvt(W2)
// ---------------------------------------------------------------------------
extern "C" void kernel_launch(void* const* d_in, const int* in_sizes, int n_in,
                              void* d_out, int out_size)
{
    const float* x     = (const float*)d_in[0];
    const float* noise = (const float*)d_in[1];
    const float* Wg    = (const float*)d_in[2];
    const float* bg    = (const float*)d_in[3];
    const float* Wn    = (const float*)d_in[4];
    const float* bn    = (const float*)d_in[5];
    const float* W1    = (const float*)d_in[6];
    const float* b1    = (const float*)d_in[7];
    const float* W2    = (const float*)d_in[8];
    const float* b2    = (const float*)d_in[9];
    float* out = (float*)d_out;

    // streams/events: created once, reused (no device work depends on this;
    // the launched graph is identical on every call)
    static cudaStream_t s1 = nullptr, s2 = nullptr;
    static cudaEvent_t  eR = nullptr, e1 = nullptr, e2 = nullptr;
    if (s1 == nullptr) {
        cudaStreamCreateWithFlags(&s1, cudaStreamNonBlocking);
        cudaStreamCreateWithFlags(&s2, cudaStreamNonBlocking);
        cudaEventCreateWithFlags(&eR, cudaEventDisableTiming);
        cudaEventCreateWithFlags(&e1, cudaEventDisableTiming);
        cudaEventCreateWithFlags(&e2, cudaEventDisableTiming);
        cudaFuncSetAttribute(gemm_f16_kernel<0>,
                             cudaFuncAttributeMaxDynamicSharedMemorySize, SMEM_TOT);
        cudaFuncSetAttribute(gemm_f16_kernel<1>,
                             cudaFuncAttributeMaxDynamicSharedMemorySize, SMEM_TOT);
    }

    __half* xh;  cudaGetSymbolAddress((void**)&xh,  g_xh);
    __half* w1h; cudaGetSymbolAddress((void**)&w1h, g_W1h);
    __half* w2h; cudaGetSymbolAddress((void**)&w2h, g_W2h);
    const int nx8 = T * D / 8;
    const int nw8 = E * DFF * D / 8;

    // s0: reset, then fork
    reset_kernel<<<1, 32>>>();
    cudaEventRecord(eR, 0);

    // s1: router (independent of cvt; needs g_cnt reset)
    cudaStreamWaitEvent(s1, eR, 0);
    router_kernel<<<T / 8, 256, 0, s1>>>(x, noise, Wg, bg, Wn, bn);
    cudaEventRecord(e1, s1);

    // s2: cvt W2 (only needed by GEMM2)
    cudaStreamWaitEvent(s2, eR, 0);
    cvt1_kernel<<<(nw8 + 255) / 256, 256, 0, s2>>>(W2, w2h, nw8);
    cudaEventRecord(e2, s2);

    // s0: cvt x + W1 (needed by GEMM1), runs concurrent with s1/s2
    cvt2_kernel<<<(nx8 + nw8 + 255) / 256, 256>>>(x, W1, xh, w1h, nx8, nw8);

    // s0: GEMM1 after router joins
    cudaStreamWaitEvent(0, e1, 0);
    {
        dim3 grid(DFF / BN, T / BM, E);
        gemm_f16_kernel<0><<<grid, 256, SMEM_TOT>>>(w1h, b1);
    }

    // s0: GEMM2 after W2 cvt joins
    cudaStreamWaitEvent(0, e2, 0);
    {
        dim3 grid(D / BN, T / BM, SPLITK * E);
        gemm_f16_kernel<1><<<grid, 256, SMEM_TOT>>>(w2h, b2);
    }

    combine_kernel<<<T, D / 4>>>(out);
}